// round 5
// baseline (speedup 1.0000x reference)
#include <cuda_runtime.h>
#include <math.h>

#define Bv   2
#define Tv   2048
#define Dv   768
#define Hv   12
#define HDv  64
#define Lv   4
#define DFv  3072
#define Vv   32000
#define Mv   (Bv*Tv)        /* 4096 rows */
#define QKVN (3*Hv*HDv)     /* 2304 */

// ---------------- scratch (static device globals; no allocs) ----------------
__device__ float g_x  [Mv*Dv];     // residual stream
__device__ float g_ln [Mv*Dv];     // layernorm output
__device__ float g_qkv[Mv*QKVN];   // qkv projection
__device__ float g_att[Mv*Dv];     // attention output
__device__ float g_ff [Mv*DFv];    // ffn hidden

// ---------------- embedding ----------------
__global__ void embed_k(const int* __restrict__ ids, const float* __restrict__ te,
                        const float* __restrict__ pe, float* __restrict__ x) {
    int i = blockIdx.x * blockDim.x + threadIdx.x;
    if (i >= Mv * Dv) return;
    int r = i / Dv, d = i - r * Dv;
    int t = r % Tv;
    x[i] = te[(size_t)ids[r] * Dv + d] + pe[(size_t)t * Dv + d];
}

// ---------------- layernorm: one block (256 thr) per row of 768 ----------------
__global__ void ln_k(const float* __restrict__ x, const float* __restrict__ s,
                     const float* __restrict__ bb, float* __restrict__ y) {
    int r = blockIdx.x;
    const float* xr = x + (size_t)r * Dv;
    float*       yr = y + (size_t)r * Dv;
    __shared__ float red[8];
    int tid = threadIdx.x; // 256
    float v0 = xr[tid], v1 = xr[tid + 256], v2 = xr[tid + 512];
    float sum = v0 + v1 + v2;
    #pragma unroll
    for (int o = 16; o; o >>= 1) sum += __shfl_xor_sync(0xffffffffu, sum, o);
    if ((tid & 31) == 0) red[tid >> 5] = sum;
    __syncthreads();
    float mu = (red[0]+red[1]+red[2]+red[3]+red[4]+red[5]+red[6]+red[7]) * (1.0f/Dv);
    float d0 = v0 - mu, d1 = v1 - mu, d2 = v2 - mu;
    float sq = d0*d0 + d1*d1 + d2*d2;
    __syncthreads();
    #pragma unroll
    for (int o = 16; o; o >>= 1) sq += __shfl_xor_sync(0xffffffffu, sq, o);
    if ((tid & 31) == 0) red[tid >> 5] = sq;
    __syncthreads();
    float var = (red[0]+red[1]+red[2]+red[3]+red[4]+red[5]+red[6]+red[7]) * (1.0f/Dv);
    float rstd = rsqrtf(var + 1e-5f);
    yr[tid      ] = d0 * rstd * s[tid      ] + bb[tid      ];
    yr[tid + 256] = d1 * rstd * s[tid + 256] + bb[tid + 256];
    yr[tid + 512] = d2 * rstd * s[tid + 512] + bb[tid + 512];
}

// ---------------- TF32 helpers ----------------
__device__ __forceinline__ unsigned f2t(float f) {
    unsigned u; asm("cvt.rna.tf32.f32 %0, %1;" : "=r"(u) : "f"(f)); return u;
}
__device__ __forceinline__ void mma_tf32(float* c, const unsigned* a, const unsigned* b) {
    asm volatile(
        "mma.sync.aligned.m16n8k8.row.col.f32.tf32.tf32.f32 "
        "{%0,%1,%2,%3}, {%4,%5,%6,%7}, {%8,%9}, {%0,%1,%2,%3};\n"
        : "+f"(c[0]), "+f"(c[1]), "+f"(c[2]), "+f"(c[3])
        : "r"(a[0]), "r"(a[1]), "r"(a[2]), "r"(a[3]), "r"(b[0]), "r"(b[1]));
}

// ---------------- Tensor-core GEMM: C[M,N] = A[M,K] @ B (+bias)(+silu)(+res) ----
// 256x128 block tile, BK=16, 256 thr = 8 warps (4x2), warp tile 64x64.
// Double-buffered dynamic SMEM, conflict-free pads.
#define APAD 20
#define BPAD 136
#define GEMM_SMEM ((2*256*APAD + 2*16*BPAD) * 4)
#define AS(buf,m,k) As[((buf)*256 + (m))*APAD + (k)]
#define BS(buf,k,n) Bs[((buf)*16 + (k))*BPAD + (n)]

template <bool TRANSB, int ACT, bool RES>
__global__ __launch_bounds__(256, 1) void gemm_tc(
    const float* __restrict__ A, const float* __restrict__ B,
    const float* __restrict__ bias, const float* __restrict__ res,
    float* __restrict__ C, int M, int N, int K) {
    extern __shared__ unsigned gsm[];
    unsigned* As = gsm;                    // [2][256][APAD]
    unsigned* Bs = gsm + 2 * 256 * APAD;   // [2][16][BPAD]

    const int tid  = threadIdx.x;
    const int lane = tid & 31, warp = tid >> 5;
    const int wm = warp >> 1, wn = warp & 1;          // 4 x 2 warps, 64x64 each
    const int m0 = blockIdx.y * 256, n0 = blockIdx.x * 128;

    float acc[4][8][4];
    #pragma unroll
    for (int i = 0; i < 4; i++)
        #pragma unroll
        for (int j = 0; j < 8; j++)
            #pragma unroll
            for (int q = 0; q < 4; q++) acc[i][j][q] = 0.0f;

    // A staging: each thread owns one row (256 rows), 16 k values = 4 float4
    const int arow = tid;
    // B staging (KxN): 16 rows x 128 n; thread -> (row=tid>>4, 8 n) = 2 float4
    const int brow = tid >> 4, bnoff = (tid & 15) * 8;
    // B^T staging (NxK): 128 n rows; thread -> (n=tid>>1, 8 k)
    const int tbn  = tid >> 1, tbk   = (tid & 1) * 8;

    float4 ra[4]; float4 rb0, rb1;
    auto loadg = [&](int k0) {
        const float* ap = A + (size_t)(m0 + arow) * K + k0;
        ra[0] = *(const float4*)ap;       ra[1] = *(const float4*)(ap + 4);
        ra[2] = *(const float4*)(ap + 8); ra[3] = *(const float4*)(ap + 12);
        if (!TRANSB) {
            const float* bp = B + (size_t)(k0 + brow) * N + n0 + bnoff;
            rb0 = *(const float4*)bp; rb1 = *(const float4*)(bp + 4);
        } else {
            const float* bp = B + (size_t)(n0 + tbn) * K + k0 + tbk;
            rb0 = *(const float4*)bp; rb1 = *(const float4*)(bp + 4);
        }
    };
    auto stores = [&](int buf) {
        uint4* a = (uint4*)&AS(buf, arow, 0);
        #pragma unroll
        for (int q = 0; q < 4; q++)
            a[q] = make_uint4(f2t(ra[q].x), f2t(ra[q].y), f2t(ra[q].z), f2t(ra[q].w));
        if (!TRANSB) {
            uint4* b = (uint4*)&BS(buf, brow, bnoff);
            b[0] = make_uint4(f2t(rb0.x), f2t(rb0.y), f2t(rb0.z), f2t(rb0.w));
            b[1] = make_uint4(f2t(rb1.x), f2t(rb1.y), f2t(rb1.z), f2t(rb1.w));
        } else {
            BS(buf, tbk + 0, tbn) = f2t(rb0.x); BS(buf, tbk + 1, tbn) = f2t(rb0.y);
            BS(buf, tbk + 2, tbn) = f2t(rb0.z); BS(buf, tbk + 3, tbn) = f2t(rb0.w);
            BS(buf, tbk + 4, tbn) = f2t(rb1.x); BS(buf, tbk + 5, tbn) = f2t(rb1.y);
            BS(buf, tbk + 6, tbn) = f2t(rb1.z); BS(buf, tbk + 7, tbn) = f2t(rb1.w);
        }
    };

    loadg(0);
    stores(0);
    __syncthreads();

    int cur = 0;
    for (int k0 = 0; k0 < K; k0 += 16) {
        bool more = (k0 + 16) < K;
        if (more) loadg(k0 + 16);

        #pragma unroll
        for (int ks = 0; ks < 2; ks++) {
            const int kb = ks * 8;
            unsigned af[4][4], bf[8][2];
            #pragma unroll
            for (int mt = 0; mt < 4; mt++) {
                int m = wm * 64 + mt * 16 + (lane >> 2);
                int k = kb + (lane & 3);
                af[mt][0] = AS(cur, m,     k    );
                af[mt][1] = AS(cur, m + 8, k    );
                af[mt][2] = AS(cur, m,     k + 4);
                af[mt][3] = AS(cur, m + 8, k + 4);
            }
            #pragma unroll
            for (int nt = 0; nt < 8; nt++) {
                int n = wn * 64 + nt * 8 + (lane >> 2);
                int k = kb + (lane & 3);
                bf[nt][0] = BS(cur, k,     n);
                bf[nt][1] = BS(cur, k + 4, n);
            }
            #pragma unroll
            for (int mt = 0; mt < 4; mt++)
                #pragma unroll
                for (int nt = 0; nt < 8; nt++)
                    mma_tf32(acc[mt][nt], af[mt], bf[nt]);
        }
        if (more) {
            stores(cur ^ 1);
            __syncthreads();
            cur ^= 1;
        }
    }

    #pragma unroll
    for (int mt = 0; mt < 4; mt++) {
        int r0 = m0 + wm * 64 + mt * 16 + (lane >> 2);
        #pragma unroll
        for (int nt = 0; nt < 8; nt++) {
            int c0i = n0 + wn * 64 + nt * 8 + 2 * (lane & 3);
            #pragma unroll
            for (int half = 0; half < 2; half++) {
                int r = r0 + half * 8;
                float v0 = acc[mt][nt][half * 2 + 0];
                float v1 = acc[mt][nt][half * 2 + 1];
                if (bias) { v0 += bias[c0i]; v1 += bias[c0i + 1]; }
                if (ACT == 1) {
                    v0 = v0 * (1.0f / (1.0f + __expf(-v0)));
                    v1 = v1 * (1.0f / (1.0f + __expf(-v1)));
                }
                if (RES) {
                    const float* rp = res + (size_t)r * N + c0i;
                    v0 += rp[0]; v1 += rp[1];
                }
                float2* cp = (float2*)(C + (size_t)r * N + c0i);
                *cp = make_float2(v0, v1);
            }
        }
    }
}

// ---------------- flash attention: 64 queries x one (b,h) per block ------------
#define QPAD 68
#define VPAD 72
#define ATTN_SMEM ((64*QPAD + 64*QPAD + 64*VPAD + 64*QPAD + 3*64) * 4)

__global__ __launch_bounds__(256) void attn_flash_k(
    const float* __restrict__ qkv, float* __restrict__ out) {
    extern __shared__ unsigned smem[];
    unsigned* Qs = smem;                       // [64][QPAD]
    unsigned* Ks = Qs + 64 * QPAD;             // [64][QPAD]
    unsigned* Vs = Ks + 64 * QPAD;             // [64][VPAD]
    float*    Ss = (float*)(Vs + 64 * VPAD);   // [64][QPAD]
    float*    m_sm = Ss + 64 * QPAD;           // [64]
    float*    l_sm = m_sm + 64;                // [64]
    float*    sc_sm = l_sm + 64;               // [64]

    const int q0 = blockIdx.x * 64;
    const int h  = blockIdx.y;
    const int b  = blockIdx.z;
    const int tid = threadIdx.x;
    const int lane = tid & 31, warp = tid >> 5;
    const int wm = warp >> 1, wn = warp & 1;   // 4 x 2

    const float* qbase = qkv + (size_t)(b * Tv) * QKVN + h * HDv;
    const float* kbase = qbase + Hv * HDv;
    const float* vbase = qbase + 2 * Hv * HDv;

    #pragma unroll
    for (int it = 0; it < 4; it++) {
        int e = tid + 256 * it;
        int r = e >> 4, d = (e & 15) * 4;
        float4 q4 = *(const float4*)(qbase + (size_t)(q0 + r) * QKVN + d);
        unsigned* dst = Qs + r * QPAD + d;
        dst[0] = f2t(q4.x * 0.125f); dst[1] = f2t(q4.y * 0.125f);
        dst[2] = f2t(q4.z * 0.125f); dst[3] = f2t(q4.w * 0.125f);
    }
    if (tid < 64) { m_sm[tid] = -1e30f; l_sm[tid] = 0.0f; }

    float acc_o[4][4];
    #pragma unroll
    for (int i = 0; i < 4; i++)
        #pragma unroll
        for (int j = 0; j < 4; j++) acc_o[i][j] = 0.0f;

    for (int c0 = 0; c0 <= q0; c0 += 64) {
        #pragma unroll
        for (int it = 0; it < 4; it++) {
            int e = tid + 256 * it;
            int r = e >> 4, d = (e & 15) * 4;
            float4 k4 = *(const float4*)(kbase + (size_t)(c0 + r) * QKVN + d);
            unsigned* kd = Ks + r * QPAD + d;
            kd[0] = f2t(k4.x); kd[1] = f2t(k4.y); kd[2] = f2t(k4.z); kd[3] = f2t(k4.w);
            float4 v4 = *(const float4*)(vbase + (size_t)(c0 + r) * QKVN + d);
            unsigned* vd = Vs + r * VPAD + d;
            vd[0] = f2t(v4.x); vd[1] = f2t(v4.y); vd[2] = f2t(v4.z); vd[3] = f2t(v4.w);
        }
        __syncthreads();

        float s_acc[4][4];
        #pragma unroll
        for (int i = 0; i < 4; i++)
            #pragma unroll
            for (int j = 0; j < 4; j++) s_acc[i][j] = 0.0f;
        #pragma unroll
        for (int kb = 0; kb < 64; kb += 8) {
            unsigned af[4], bf[4][2];
            int mr = wm * 16 + (lane >> 2);
            int kk = kb + (lane & 3);
            af[0] = Qs[mr * QPAD + kk];
            af[1] = Qs[(mr + 8) * QPAD + kk];
            af[2] = Qs[mr * QPAD + kk + 4];
            af[3] = Qs[(mr + 8) * QPAD + kk + 4];
            #pragma unroll
            for (int nt = 0; nt < 4; nt++) {
                int n = wn * 32 + nt * 8 + (lane >> 2);
                bf[nt][0] = Ks[n * QPAD + kb + (lane & 3)];
                bf[nt][1] = Ks[n * QPAD + kb + (lane & 3) + 4];
            }
            #pragma unroll
            for (int nt = 0; nt < 4; nt++)
                mma_tf32(s_acc[nt], af, bf[nt]);
        }
        const bool diag = (c0 == q0);
        #pragma unroll
        for (int nt = 0; nt < 4; nt++) {
            int c = wn * 32 + nt * 8 + 2 * (lane & 3);
            #pragma unroll
            for (int half = 0; half < 2; half++) {
                int r = wm * 16 + (lane >> 2) + half * 8;
                float v0 = s_acc[nt][half * 2 + 0];
                float v1 = s_acc[nt][half * 2 + 1];
                if (diag) {
                    if (c     > r) v0 = -1e30f;
                    if (c + 1 > r) v1 = -1e30f;
                }
                Ss[r * QPAD + c] = v0; Ss[r * QPAD + c + 1] = v1;
            }
        }
        __syncthreads();

        {
            int r = tid >> 2, g = tid & 3;
            float* row = Ss + r * QPAD;
            float cmax = -1e30f;
            #pragma unroll
            for (int j = 0; j < 16; j++) cmax = fmaxf(cmax, row[g + 4 * j]);
            cmax = fmaxf(cmax, __shfl_xor_sync(0xffffffffu, cmax, 1));
            cmax = fmaxf(cmax, __shfl_xor_sync(0xffffffffu, cmax, 2));
            float m_old = m_sm[r];
            float m_new = fmaxf(m_old, cmax);
            float csum = 0.0f;
            unsigned* prow = (unsigned*)row;
            #pragma unroll
            for (int j = 0; j < 16; j++) {
                float p = __expf(row[g + 4 * j] - m_new);
                csum += p;
                prow[g + 4 * j] = f2t(p);
            }
            csum += __shfl_xor_sync(0xffffffffu, csum, 1);
            csum += __shfl_xor_sync(0xffffffffu, csum, 2);
            if (g == 0) {
                float scale = __expf(m_old - m_new);
                sc_sm[r] = scale;
                l_sm[r] = l_sm[r] * scale + csum;
                m_sm[r] = m_new;
            }
        }
        __syncthreads();

        {
            int r1 = wm * 16 + (lane >> 2);
            float s1 = sc_sm[r1], s2 = sc_sm[r1 + 8];
            #pragma unroll
            for (int nt = 0; nt < 4; nt++) {
                acc_o[nt][0] *= s1; acc_o[nt][1] *= s1;
                acc_o[nt][2] *= s2; acc_o[nt][3] *= s2;
            }
        }
        const unsigned* Pu = (const unsigned*)Ss;
        #pragma unroll
        for (int kb = 0; kb < 64; kb += 8) {
            unsigned af[4], bf[4][2];
            int mr = wm * 16 + (lane >> 2);
            int kk = kb + (lane & 3);
            af[0] = Pu[mr * QPAD + kk];
            af[1] = Pu[(mr + 8) * QPAD + kk];
            af[2] = Pu[mr * QPAD + kk + 4];
            af[3] = Pu[(mr + 8) * QPAD + kk + 4];
            #pragma unroll
            for (int nt = 0; nt < 4; nt++) {
                int n = wn * 32 + nt * 8 + (lane >> 2);
                bf[nt][0] = Vs[(kb + (lane & 3)) * VPAD + n];
                bf[nt][1] = Vs[(kb + (lane & 3) + 4) * VPAD + n];
            }
            #pragma unroll
            for (int nt = 0; nt < 4; nt++)
                mma_tf32(acc_o[nt], af, bf[nt]);
        }
        __syncthreads();
    }

    {
        int r1 = wm * 16 + (lane >> 2);
        float inv1 = 1.0f / l_sm[r1], inv2 = 1.0f / l_sm[r1 + 8];
        #pragma unroll
        for (int nt = 0; nt < 4; nt++) {
            int c = wn * 32 + nt * 8 + 2 * (lane & 3);
            float* o1 = out + (size_t)(b * Tv + q0 + r1) * Dv + h * HDv + c;
            float* o2 = out + (size_t)(b * Tv + q0 + r1 + 8) * Dv + h * HDv + c;
            o1[0] = acc_o[nt][0] * inv1; o1[1] = acc_o[nt][1] * inv1;
            o2[0] = acc_o[nt][2] * inv2; o2[1] = acc_o[nt][3] * inv2;
        }
    }
}

// ---------------- driver ----------------
extern "C" void kernel_launch(void* const* d_in, const int* in_sizes, int n_in,
                              void* d_out, int out_size) {
    const int*   ids   = (const int*)  d_in[0];
    const float* te    = (const float*)d_in[1];
    const float* pe    = (const float*)d_in[2];
    const float* ln1_s = (const float*)d_in[3];
    const float* ln1_b = (const float*)d_in[4];
    const float* qkv_w = (const float*)d_in[5];
    const float* qkv_b = (const float*)d_in[6];
    const float* out_w = (const float*)d_in[7];
    const float* out_b = (const float*)d_in[8];
    const float* ln2_s = (const float*)d_in[9];
    const float* ln2_b = (const float*)d_in[10];
    const float* up_w  = (const float*)d_in[11];
    const float* up_b  = (const float*)d_in[12];
    const float* dn_w  = (const float*)d_in[13];
    const float* dn_b  = (const float*)d_in[14];
    const float* lnf_s = (const float*)d_in[15];
    const float* lnf_b = (const float*)d_in[16];
    float* logits = (float*)d_out;

    float *x, *lnb, *qkv, *att, *ff;
    cudaGetSymbolAddress((void**)&x,   g_x);
    cudaGetSymbolAddress((void**)&lnb, g_ln);
    cudaGetSymbolAddress((void**)&qkv, g_qkv);
    cudaGetSymbolAddress((void**)&att, g_att);
    cudaGetSymbolAddress((void**)&ff,  g_ff);

    cudaFuncSetAttribute(attn_flash_k,
                         cudaFuncAttributeMaxDynamicSharedMemorySize, ATTN_SMEM);
    cudaFuncSetAttribute(gemm_tc<false, 0, false>,
                         cudaFuncAttributeMaxDynamicSharedMemorySize, GEMM_SMEM);
    cudaFuncSetAttribute(gemm_tc<false, 0, true>,
                         cudaFuncAttributeMaxDynamicSharedMemorySize, GEMM_SMEM);
    cudaFuncSetAttribute(gemm_tc<false, 1, false>,
                         cudaFuncAttributeMaxDynamicSharedMemorySize, GEMM_SMEM);
    cudaFuncSetAttribute(gemm_tc<true, 0, false>,
                         cudaFuncAttributeMaxDynamicSharedMemorySize, GEMM_SMEM);

    embed_k<<<(Mv * Dv + 255) / 256, 256>>>(ids, te, pe, x);

    for (int i = 0; i < Lv; i++) {
        ln_k<<<Mv, 256>>>(x, ln1_s + (size_t)i * Dv, ln1_b + (size_t)i * Dv, lnb);
        gemm_tc<false, 0, false><<<dim3(QKVN / 128, Mv / 256), 256, GEMM_SMEM>>>(
            lnb, qkv_w + (size_t)i * Dv * QKVN, qkv_b + (size_t)i * QKVN,
            nullptr, qkv, Mv, QKVN, Dv);
        attn_flash_k<<<dim3(Tv / 64, Hv, Bv), 256, ATTN_SMEM>>>(qkv, att);
        gemm_tc<false, 0, true><<<dim3(Dv / 128, Mv / 256), 256, GEMM_SMEM>>>(
            att, out_w + (size_t)i * Dv * Dv, out_b + (size_t)i * Dv,
            x, x, Mv, Dv, Dv);
        ln_k<<<Mv, 256>>>(x, ln2_s + (size_t)i * Dv, ln2_b + (size_t)i * Dv, lnb);
        gemm_tc<false, 1, false><<<dim3(DFv / 128, Mv / 256), 256, GEMM_SMEM>>>(
            lnb, up_w + (size_t)i * Dv * DFv, up_b + (size_t)i * DFv,
            nullptr, ff, Mv, DFv, Dv);
        gemm_tc<false, 0, true><<<dim3(Dv / 128, Mv / 256), 256, GEMM_SMEM>>>(
            ff, dn_w + (size_t)i * DFv * Dv, dn_b + (size_t)i * Dv,
            x, x, Mv, Dv, DFv);
    }

    ln_k<<<Mv, 256>>>(x, lnf_s, lnf_b, lnb);
    gemm_tc<true, 0, false><<<dim3(Vv / 128, Mv / 256), 256, GEMM_SMEM>>>(
        lnb, te, nullptr, nullptr, logits, Mv, Vv, Dv);
}

// round 6
// speedup vs baseline: 1.3279x; 1.3279x over previous
#include <cuda_runtime.h>
#include <math.h>

#define Bv   2
#define Tv   2048
#define Dv   768
#define Hv   12
#define HDv  64
#define Lv   4
#define DFv  3072
#define Vv   32000
#define Mv   (Bv*Tv)        /* 4096 rows */
#define QKVN (3*Hv*HDv)     /* 2304 */

// ---------------- scratch (static device globals; no allocs) ----------------
__device__ float g_x  [Mv*Dv];     // residual stream
__device__ float g_ln [Mv*Dv];     // layernorm output
__device__ float g_qkv[Mv*QKVN];   // qkv projection
__device__ float g_att[Mv*Dv];     // attention output
__device__ float g_ff [Mv*DFv];    // ffn hidden

// ---------------- embedding ----------------
__global__ void embed_k(const int* __restrict__ ids, const float* __restrict__ te,
                        const float* __restrict__ pe, float* __restrict__ x) {
    int i = blockIdx.x * blockDim.x + threadIdx.x;
    if (i >= Mv * Dv) return;
    int r = i / Dv, d = i - r * Dv;
    int t = r % Tv;
    x[i] = te[(size_t)ids[r] * Dv + d] + pe[(size_t)t * Dv + d];
}

// ---------------- layernorm: one block (256 thr) per row of 768 ----------------
__global__ void ln_k(const float* __restrict__ x, const float* __restrict__ s,
                     const float* __restrict__ bb, float* __restrict__ y) {
    int r = blockIdx.x;
    const float* xr = x + (size_t)r * Dv;
    float*       yr = y + (size_t)r * Dv;
    __shared__ float red[8];
    int tid = threadIdx.x; // 256
    float v0 = xr[tid], v1 = xr[tid + 256], v2 = xr[tid + 512];
    float sum = v0 + v1 + v2;
    #pragma unroll
    for (int o = 16; o; o >>= 1) sum += __shfl_xor_sync(0xffffffffu, sum, o);
    if ((tid & 31) == 0) red[tid >> 5] = sum;
    __syncthreads();
    float mu = (red[0]+red[1]+red[2]+red[3]+red[4]+red[5]+red[6]+red[7]) * (1.0f/Dv);
    float d0 = v0 - mu, d1 = v1 - mu, d2 = v2 - mu;
    float sq = d0*d0 + d1*d1 + d2*d2;
    __syncthreads();
    #pragma unroll
    for (int o = 16; o; o >>= 1) sq += __shfl_xor_sync(0xffffffffu, sq, o);
    if ((tid & 31) == 0) red[tid >> 5] = sq;
    __syncthreads();
    float var = (red[0]+red[1]+red[2]+red[3]+red[4]+red[5]+red[6]+red[7]) * (1.0f/Dv);
    float rstd = rsqrtf(var + 1e-5f);
    yr[tid      ] = d0 * rstd * s[tid      ] + bb[tid      ];
    yr[tid + 256] = d1 * rstd * s[tid + 256] + bb[tid + 256];
    yr[tid + 512] = d2 * rstd * s[tid + 512] + bb[tid + 512];
}

// ---------------- TF32 / async helpers ----------------
__device__ __forceinline__ unsigned f2t(float f) {
    unsigned u; asm("cvt.rna.tf32.f32 %0, %1;" : "=r"(u) : "f"(f)); return u;
}
__device__ __forceinline__ void mma_tf32(float* c, const unsigned* a, const unsigned* b) {
    asm volatile(
        "mma.sync.aligned.m16n8k8.row.col.f32.tf32.tf32.f32 "
        "{%0,%1,%2,%3}, {%4,%5,%6,%7}, {%8,%9}, {%0,%1,%2,%3};\n"
        : "+f"(c[0]), "+f"(c[1]), "+f"(c[2]), "+f"(c[3])
        : "r"(a[0]), "r"(a[1]), "r"(a[2]), "r"(a[3]), "r"(b[0]), "r"(b[1]));
}
__device__ __forceinline__ void cp16(unsigned sdst, const float* g) {
    asm volatile("cp.async.cg.shared.global [%0], [%1], 16;" :: "r"(sdst), "l"(g));
}
__device__ __forceinline__ void cp_commit() {
    asm volatile("cp.async.commit_group;");
}
template <int N>
__device__ __forceinline__ void cp_wait() {
    asm volatile("cp.async.wait_group %0;" :: "n"(N));
}

// ---------------- Tensor-core GEMM: C[M,N] = A[M,K] @ B (+bias)(+silu)(+res) ----
// 128x128 tile, BK=16, 256 thr = 8 warps (4x2), warp tile 32x64.
// 5-stage cp.async pipeline, fp32 staged raw, cvt.rna at fragment load.
#define APAD 20    /* float stride; 80B rows (16B aligned), conflict-free frag reads */
#define BPAD 136
#define NSTAGE 5
#define AW (128*APAD)                 /* words per stage, A */

template <bool TRANSB, int ACT, bool RES>
__global__ __launch_bounds__(256, 2) void gemm_tc(
    const float* __restrict__ A, const float* __restrict__ B,
    const float* __restrict__ bias, const float* __restrict__ res,
    float* __restrict__ C, int M, int N, int K) {
    constexpr int BW = TRANSB ? 128 * APAD : 16 * BPAD;
    constexpr int SW = AW + BW;       /* words per stage */
    extern __shared__ float gsm[];

    const int tid  = threadIdx.x;
    const int lane = tid & 31, warp = tid >> 5;
    const int wm = warp >> 1, wn = warp & 1;          // 4 x 2 warps
    const int m0 = blockIdx.y * 128, n0 = blockIdx.x * 128;
    const unsigned sbase = (unsigned)__cvta_generic_to_shared(gsm);

    float acc[2][8][4];
    #pragma unroll
    for (int i = 0; i < 2; i++)
        #pragma unroll
        for (int j = 0; j < 8; j++)
            #pragma unroll
            for (int q = 0; q < 4; q++) acc[i][j][q] = 0.0f;

    const int arow = tid >> 1, akoff = (tid & 1) * 8;   // A: 128 rows x 16 k
    const int brow = tid >> 4, bnoff = (tid & 15) * 8;  // B [k][n]
    const int tbn  = tid >> 1, tbk   = (tid & 1) * 8;   // B^T [n][k]

    auto issue = [&](int stg, int k0) {
        const float* ap = A + (size_t)(m0 + arow) * K + k0 + akoff;
        unsigned ad = sbase + (stg * SW + arow * APAD + akoff) * 4;
        cp16(ad, ap); cp16(ad + 16, ap + 4);
        if (!TRANSB) {
            const float* bp = B + (size_t)(k0 + brow) * N + n0 + bnoff;
            unsigned bd = sbase + (stg * SW + AW + brow * BPAD + bnoff) * 4;
            cp16(bd, bp); cp16(bd + 16, bp + 4);
        } else {
            const float* bp = B + (size_t)(n0 + tbn) * K + k0 + tbk;
            unsigned bd = sbase + (stg * SW + AW + tbn * APAD + tbk) * 4;
            cp16(bd, bp); cp16(bd + 16, bp + 4);
        }
    };

    const int nslab = K / 16;
    #pragma unroll
    for (int s = 0; s < NSTAGE - 1; s++) {
        if (s < nslab) issue(s, s * 16);
        cp_commit();
    }

    for (int i = 0; i < nslab; i++) {
        cp_wait<NSTAGE - 2>();
        __syncthreads();

        const float* Asf = gsm + (i % NSTAGE) * SW;
        const float* Bsf = Asf + AW;

        #pragma unroll
        for (int ks = 0; ks < 2; ks++) {
            const int kb = ks * 8;
            unsigned af[2][4], bf[8][2];
            #pragma unroll
            for (int mt = 0; mt < 2; mt++) {
                int m = wm * 32 + mt * 16 + (lane >> 2);
                int k = kb + (lane & 3);
                af[mt][0] = f2t(Asf[m * APAD + k]);
                af[mt][1] = f2t(Asf[(m + 8) * APAD + k]);
                af[mt][2] = f2t(Asf[m * APAD + k + 4]);
                af[mt][3] = f2t(Asf[(m + 8) * APAD + k + 4]);
            }
            #pragma unroll
            for (int nt = 0; nt < 8; nt++) {
                int n = wn * 64 + nt * 8 + (lane >> 2);
                int k = kb + (lane & 3);
                if (!TRANSB) {
                    bf[nt][0] = f2t(Bsf[k * BPAD + n]);
                    bf[nt][1] = f2t(Bsf[(k + 4) * BPAD + n]);
                } else {
                    bf[nt][0] = f2t(Bsf[n * APAD + k]);
                    bf[nt][1] = f2t(Bsf[n * APAD + k + 4]);
                }
            }
            #pragma unroll
            for (int mt = 0; mt < 2; mt++)
                #pragma unroll
                for (int nt = 0; nt < 8; nt++)
                    mma_tf32(acc[mt][nt], af[mt], bf[nt]);
        }

        int j = i + NSTAGE - 1;
        if (j < nslab) issue(j % NSTAGE, j * 16);
        cp_commit();
    }

    #pragma unroll
    for (int mt = 0; mt < 2; mt++) {
        int r0 = m0 + wm * 32 + mt * 16 + (lane >> 2);
        #pragma unroll
        for (int nt = 0; nt < 8; nt++) {
            int c0i = n0 + wn * 64 + nt * 8 + 2 * (lane & 3);
            #pragma unroll
            for (int half = 0; half < 2; half++) {
                int r = r0 + half * 8;
                float v0 = acc[mt][nt][half * 2 + 0];
                float v1 = acc[mt][nt][half * 2 + 1];
                if (bias) { v0 += bias[c0i]; v1 += bias[c0i + 1]; }
                if (ACT == 1) {
                    v0 = v0 * (1.0f / (1.0f + __expf(-v0)));
                    v1 = v1 * (1.0f / (1.0f + __expf(-v1)));
                }
                if (RES) {
                    const float* rp = res + (size_t)r * N + c0i;
                    v0 += rp[0]; v1 += rp[1];
                }
                float2* cp = (float2*)(C + (size_t)r * N + c0i);
                *cp = make_float2(v0, v1);
            }
        }
    }
}
#define GEMM_SMEM_NT (NSTAGE * (AW + 16 * BPAD) * 4)
#define GEMM_SMEM_T  (NSTAGE * (AW + 128 * APAD) * 4)

// ---------------- flash attention: 64 queries x one (b,h) per block ------------
#define QPAD 68
#define VPAD 72
#define ATTN_SMEM ((64*QPAD + 64*QPAD + 64*VPAD + 64*QPAD + 3*64) * 4)

__global__ __launch_bounds__(256) void attn_flash_k(
    const float* __restrict__ qkv, float* __restrict__ out) {
    extern __shared__ unsigned smem[];
    unsigned* Qs = smem;                       // [64][QPAD]
    unsigned* Ks = Qs + 64 * QPAD;             // [64][QPAD]
    unsigned* Vs = Ks + 64 * QPAD;             // [64][VPAD]
    float*    Ss = (float*)(Vs + 64 * VPAD);   // [64][QPAD]
    float*    m_sm = Ss + 64 * QPAD;           // [64]
    float*    l_sm = m_sm + 64;                // [64]
    float*    sc_sm = l_sm + 64;               // [64]

    const int q0 = blockIdx.x * 64;
    const int h  = blockIdx.y;
    const int b  = blockIdx.z;
    const int tid = threadIdx.x;
    const int lane = tid & 31, warp = tid >> 5;
    const int wm = warp >> 1, wn = warp & 1;   // 4 x 2

    const float* qbase = qkv + (size_t)(b * Tv) * QKVN + h * HDv;
    const float* kbase = qbase + Hv * HDv;
    const float* vbase = qbase + 2 * Hv * HDv;

    #pragma unroll
    for (int it = 0; it < 4; it++) {
        int e = tid + 256 * it;
        int r = e >> 4, d = (e & 15) * 4;
        float4 q4 = *(const float4*)(qbase + (size_t)(q0 + r) * QKVN + d);
        unsigned* dst = Qs + r * QPAD + d;
        dst[0] = f2t(q4.x * 0.125f); dst[1] = f2t(q4.y * 0.125f);
        dst[2] = f2t(q4.z * 0.125f); dst[3] = f2t(q4.w * 0.125f);
    }
    if (tid < 64) { m_sm[tid] = -1e30f; l_sm[tid] = 0.0f; }

    float acc_o[4][4];
    #pragma unroll
    for (int i = 0; i < 4; i++)
        #pragma unroll
        for (int j = 0; j < 4; j++) acc_o[i][j] = 0.0f;

    for (int c0 = 0; c0 <= q0; c0 += 64) {
        #pragma unroll
        for (int it = 0; it < 4; it++) {
            int e = tid + 256 * it;
            int r = e >> 4, d = (e & 15) * 4;
            float4 k4 = *(const float4*)(kbase + (size_t)(c0 + r) * QKVN + d);
            unsigned* kd = Ks + r * QPAD + d;
            kd[0] = f2t(k4.x); kd[1] = f2t(k4.y); kd[2] = f2t(k4.z); kd[3] = f2t(k4.w);
            float4 v4 = *(const float4*)(vbase + (size_t)(c0 + r) * QKVN + d);
            unsigned* vd = Vs + r * VPAD + d;
            vd[0] = f2t(v4.x); vd[1] = f2t(v4.y); vd[2] = f2t(v4.z); vd[3] = f2t(v4.w);
        }
        __syncthreads();

        float s_acc[4][4];
        #pragma unroll
        for (int i = 0; i < 4; i++)
            #pragma unroll
            for (int j = 0; j < 4; j++) s_acc[i][j] = 0.0f;
        #pragma unroll
        for (int kb = 0; kb < 64; kb += 8) {
            unsigned af[4], bf[4][2];
            int mr = wm * 16 + (lane >> 2);
            int kk = kb + (lane & 3);
            af[0] = Qs[mr * QPAD + kk];
            af[1] = Qs[(mr + 8) * QPAD + kk];
            af[2] = Qs[mr * QPAD + kk + 4];
            af[3] = Qs[(mr + 8) * QPAD + kk + 4];
            #pragma unroll
            for (int nt = 0; nt < 4; nt++) {
                int n = wn * 32 + nt * 8 + (lane >> 2);
                bf[nt][0] = Ks[n * QPAD + kb + (lane & 3)];
                bf[nt][1] = Ks[n * QPAD + kb + (lane & 3) + 4];
            }
            #pragma unroll
            for (int nt = 0; nt < 4; nt++)
                mma_tf32(s_acc[nt], af, bf[nt]);
        }
        const bool diag = (c0 == q0);
        #pragma unroll
        for (int nt = 0; nt < 4; nt++) {
            int c = wn * 32 + nt * 8 + 2 * (lane & 3);
            #pragma unroll
            for (int half = 0; half < 2; half++) {
                int r = wm * 16 + (lane >> 2) + half * 8;
                float v0 = s_acc[nt][half * 2 + 0];
                float v1 = s_acc[nt][half * 2 + 1];
                if (diag) {
                    if (c     > r) v0 = -1e30f;
                    if (c + 1 > r) v1 = -1e30f;
                }
                Ss[r * QPAD + c] = v0; Ss[r * QPAD + c + 1] = v1;
            }
        }
        __syncthreads();

        {
            int r = tid >> 2, g = tid & 3;
            float* row = Ss + r * QPAD;
            float cmax = -1e30f;
            #pragma unroll
            for (int j = 0; j < 16; j++) cmax = fmaxf(cmax, row[g + 4 * j]);
            cmax = fmaxf(cmax, __shfl_xor_sync(0xffffffffu, cmax, 1));
            cmax = fmaxf(cmax, __shfl_xor_sync(0xffffffffu, cmax, 2));
            float m_old = m_sm[r];
            float m_new = fmaxf(m_old, cmax);
            float csum = 0.0f;
            unsigned* prow = (unsigned*)row;
            #pragma unroll
            for (int j = 0; j < 16; j++) {
                float p = __expf(row[g + 4 * j] - m_new);
                csum += p;
                prow[g + 4 * j] = f2t(p);
            }
            csum += __shfl_xor_sync(0xffffffffu, csum, 1);
            csum += __shfl_xor_sync(0xffffffffu, csum, 2);
            if (g == 0) {
                float scale = __expf(m_old - m_new);
                sc_sm[r] = scale;
                l_sm[r] = l_sm[r] * scale + csum;
                m_sm[r] = m_new;
            }
        }
        __syncthreads();

        {
            int r1 = wm * 16 + (lane >> 2);
            float s1 = sc_sm[r1], s2 = sc_sm[r1 + 8];
            #pragma unroll
            for (int nt = 0; nt < 4; nt++) {
                acc_o[nt][0] *= s1; acc_o[nt][1] *= s1;
                acc_o[nt][2] *= s2; acc_o[nt][3] *= s2;
            }
        }
        const unsigned* Pu = (const unsigned*)Ss;
        #pragma unroll
        for (int kb = 0; kb < 64; kb += 8) {
            unsigned af[4], bf[4][2];
            int mr = wm * 16 + (lane >> 2);
            int kk = kb + (lane & 3);
            af[0] = Pu[mr * QPAD + kk];
            af[1] = Pu[(mr + 8) * QPAD + kk];
            af[2] = Pu[mr * QPAD + kk + 4];
            af[3] = Pu[(mr + 8) * QPAD + kk + 4];
            #pragma unroll
            for (int nt = 0; nt < 4; nt++) {
                int n = wn * 32 + nt * 8 + (lane >> 2);
                bf[nt][0] = Vs[(kb + (lane & 3)) * VPAD + n];
                bf[nt][1] = Vs[(kb + (lane & 3) + 4) * VPAD + n];
            }
            #pragma unroll
            for (int nt = 0; nt < 4; nt++)
                mma_tf32(acc_o[nt], af, bf[nt]);
        }
        __syncthreads();
    }

    {
        int r1 = wm * 16 + (lane >> 2);
        float inv1 = 1.0f / l_sm[r1], inv2 = 1.0f / l_sm[r1 + 8];
        #pragma unroll
        for (int nt = 0; nt < 4; nt++) {
            int c = wn * 32 + nt * 8 + 2 * (lane & 3);
            float* o1 = out + (size_t)(b * Tv + q0 + r1) * Dv + h * HDv + c;
            float* o2 = out + (size_t)(b * Tv + q0 + r1 + 8) * Dv + h * HDv + c;
            o1[0] = acc_o[nt][0] * inv1; o1[1] = acc_o[nt][1] * inv1;
            o2[0] = acc_o[nt][2] * inv2; o2[1] = acc_o[nt][3] * inv2;
        }
    }
}

// ---------------- driver ----------------
extern "C" void kernel_launch(void* const* d_in, const int* in_sizes, int n_in,
                              void* d_out, int out_size) {
    const int*   ids   = (const int*)  d_in[0];
    const float* te    = (const float*)d_in[1];
    const float* pe    = (const float*)d_in[2];
    const float* ln1_s = (const float*)d_in[3];
    const float* ln1_b = (const float*)d_in[4];
    const float* qkv_w = (const float*)d_in[5];
    const float* qkv_b = (const float*)d_in[6];
    const float* out_w = (const float*)d_in[7];
    const float* out_b = (const float*)d_in[8];
    const float* ln2_s = (const float*)d_in[9];
    const float* ln2_b = (const float*)d_in[10];
    const float* up_w  = (const float*)d_in[11];
    const float* up_b  = (const float*)d_in[12];
    const float* dn_w  = (const float*)d_in[13];
    const float* dn_b  = (const float*)d_in[14];
    const float* lnf_s = (const float*)d_in[15];
    const float* lnf_b = (const float*)d_in[16];
    float* logits = (float*)d_out;

    float *x, *lnb, *qkv, *att, *ff;
    cudaGetSymbolAddress((void**)&x,   g_x);
    cudaGetSymbolAddress((void**)&lnb, g_ln);
    cudaGetSymbolAddress((void**)&qkv, g_qkv);
    cudaGetSymbolAddress((void**)&att, g_att);
    cudaGetSymbolAddress((void**)&ff,  g_ff);

    cudaFuncSetAttribute(attn_flash_k,
                         cudaFuncAttributeMaxDynamicSharedMemorySize, ATTN_SMEM);
    cudaFuncSetAttribute(gemm_tc<false, 0, false>,
                         cudaFuncAttributeMaxDynamicSharedMemorySize, GEMM_SMEM_NT);
    cudaFuncSetAttribute(gemm_tc<false, 0, true>,
                         cudaFuncAttributeMaxDynamicSharedMemorySize, GEMM_SMEM_NT);
    cudaFuncSetAttribute(gemm_tc<false, 1, false>,
                         cudaFuncAttributeMaxDynamicSharedMemorySize, GEMM_SMEM_NT);
    cudaFuncSetAttribute(gemm_tc<true, 0, false>,
                         cudaFuncAttributeMaxDynamicSharedMemorySize, GEMM_SMEM_T);

    embed_k<<<(Mv * Dv + 255) / 256, 256>>>(ids, te, pe, x);

    for (int i = 0; i < Lv; i++) {
        ln_k<<<Mv, 256>>>(x, ln1_s + (size_t)i * Dv, ln1_b + (size_t)i * Dv, lnb);
        gemm_tc<false, 0, false><<<dim3(QKVN / 128, Mv / 128), 256, GEMM_SMEM_NT>>>(
            lnb, qkv_w + (size_t)i * Dv * QKVN, qkv_b + (size_t)i * QKVN,
            nullptr, qkv, Mv, QKVN, Dv);
        attn_flash_k<<<dim3(Tv / 64, Hv, Bv), 256, ATTN_SMEM>>>(qkv, att);
        gemm_tc<false, 0, true><<<dim3(Dv / 128, Mv / 128), 256, GEMM_SMEM_NT>>>(
            att, out_w + (size_t)i * Dv * Dv, out_b + (size_t)i * Dv,
            x, x, Mv, Dv, Dv);
        ln_k<<<Mv, 256>>>(x, ln2_s + (size_t)i * Dv, ln2_b + (size_t)i * Dv, lnb);
        gemm_tc<false, 1, false><<<dim3(DFv / 128, Mv / 128), 256, GEMM_SMEM_NT>>>(
            lnb, up_w + (size_t)i * Dv * DFv, up_b + (size_t)i * DFv,
            nullptr, ff, Mv, DFv, Dv);
        gemm_tc<false, 0, true><<<dim3(Dv / 128, Mv / 128), 256, GEMM_SMEM_NT>>>(
            ff, dn_w + (size_t)i * DFv * Dv, dn_b + (size_t)i * Dv,
            x, x, Mv, Dv, DFv);
    }

    ln_k<<<Mv, 256>>>(x, lnf_s, lnf_b, lnb);
    gemm_tc<true, 0, false><<<dim3(Vv / 128, Mv / 128), 256, GEMM_SMEM_T>>>(
        lnb, te, nullptr, nullptr, logits, Mv, Vv, Dv);
}

// round 7
// speedup vs baseline: 1.3992x; 1.0537x over previous
#include <cuda_runtime.h>
#include <math.h>

#define Bv   2
#define Tv   2048
#define Dv   768
#define Hv   12
#define HDv  64
#define Lv   4
#define DFv  3072
#define Vv   32000
#define Mv   (Bv*Tv)        /* 4096 rows */
#define QKVN (3*Hv*HDv)     /* 2304 */

// ---------------- scratch (static device globals; no allocs) ----------------
__device__ float g_x  [Mv*Dv];     // residual stream
__device__ float g_ln [Mv*Dv];     // layernorm output (tf32-rounded)
__device__ float g_qkv[Mv*QKVN];   // qkv projection (tf32-rounded)
__device__ float g_att[Mv*Dv];     // attention output (tf32-rounded)
__device__ float g_ff [Mv*DFv];    // ffn hidden (tf32-rounded)
// tf32-canonical weight copies
__device__ float g_wqkv[Lv*Dv*QKVN];
__device__ float g_wout[Lv*Dv*Dv];
__device__ float g_wup [Lv*Dv*DFv];
__device__ float g_wdn [Lv*DFv*Dv];
__device__ float g_te  [Vv*Dv];

// ---------------- TF32 / async helpers ----------------
__device__ __forceinline__ unsigned f2t(float f) {
    unsigned u; asm("cvt.rna.tf32.f32 %0, %1;" : "=r"(u) : "f"(f)); return u;
}
__device__ __forceinline__ float f2tf(float f) { return __uint_as_float(f2t(f)); }
__device__ __forceinline__ void mma_tf32(float* c, const unsigned* a, const unsigned* b) {
    asm volatile(
        "mma.sync.aligned.m16n8k8.row.col.f32.tf32.tf32.f32 "
        "{%0,%1,%2,%3}, {%4,%5,%6,%7}, {%8,%9}, {%0,%1,%2,%3};\n"
        : "+f"(c[0]), "+f"(c[1]), "+f"(c[2]), "+f"(c[3])
        : "r"(a[0]), "r"(a[1]), "r"(a[2]), "r"(a[3]), "r"(b[0]), "r"(b[1]));
}
__device__ __forceinline__ void cp16(unsigned sdst, const float* g) {
    asm volatile("cp.async.cg.shared.global [%0], [%1], 16;" :: "r"(sdst), "l"(g));
}
__device__ __forceinline__ void cp_commit() {
    asm volatile("cp.async.commit_group;");
}
template <int N>
__device__ __forceinline__ void cp_wait() {
    asm volatile("cp.async.wait_group %0;" :: "n"(N));
}

// ---------------- weight conversion: fp32 -> tf32-canonical fp32 ----------------
__global__ void cvt_k(const float* __restrict__ in, float* __restrict__ out, int n4) {
    int i = blockIdx.x * blockDim.x + threadIdx.x;
    if (i >= n4) return;
    float4 v = ((const float4*)in)[i];
    ((float4*)out)[i] = make_float4(f2tf(v.x), f2tf(v.y), f2tf(v.z), f2tf(v.w));
}

// ---------------- embedding ----------------
__global__ void embed_k(const int* __restrict__ ids, const float* __restrict__ te,
                        const float* __restrict__ pe, float* __restrict__ x) {
    int i = blockIdx.x * blockDim.x + threadIdx.x;
    if (i >= Mv * Dv) return;
    int r = i / Dv, d = i - r * Dv;
    int t = r % Tv;
    x[i] = te[(size_t)ids[r] * Dv + d] + pe[(size_t)t * Dv + d];
}

// ---------------- layernorm (writes tf32-rounded output) ----------------
__global__ void ln_k(const float* __restrict__ x, const float* __restrict__ s,
                     const float* __restrict__ bb, float* __restrict__ y) {
    int r = blockIdx.x;
    const float* xr = x + (size_t)r * Dv;
    float*       yr = y + (size_t)r * Dv;
    __shared__ float red[8];
    int tid = threadIdx.x; // 256
    float v0 = xr[tid], v1 = xr[tid + 256], v2 = xr[tid + 512];
    float sum = v0 + v1 + v2;
    #pragma unroll
    for (int o = 16; o; o >>= 1) sum += __shfl_xor_sync(0xffffffffu, sum, o);
    if ((tid & 31) == 0) red[tid >> 5] = sum;
    __syncthreads();
    float mu = (red[0]+red[1]+red[2]+red[3]+red[4]+red[5]+red[6]+red[7]) * (1.0f/Dv);
    float d0 = v0 - mu, d1 = v1 - mu, d2 = v2 - mu;
    float sq = d0*d0 + d1*d1 + d2*d2;
    __syncthreads();
    #pragma unroll
    for (int o = 16; o; o >>= 1) sq += __shfl_xor_sync(0xffffffffu, sq, o);
    if ((tid & 31) == 0) red[tid >> 5] = sq;
    __syncthreads();
    float var = (red[0]+red[1]+red[2]+red[3]+red[4]+red[5]+red[6]+red[7]) * (1.0f/Dv);
    float rstd = rsqrtf(var + 1e-5f);
    yr[tid      ] = f2tf(d0 * rstd * s[tid      ] + bb[tid      ]);
    yr[tid + 256] = f2tf(d1 * rstd * s[tid + 256] + bb[tid + 256]);
    yr[tid + 512] = f2tf(d2 * rstd * s[tid + 512] + bb[tid + 512]);
}

// ---------------- Tensor-core GEMM: C[M,N] = A[M,K] @ B (+bias)(+silu)(+res) ----
// Inputs MUST be tf32-canonical fp32. 128x128 tile, BK=16, 8 warps (4x2),
// warp tile 32x64, 5-stage cp.async pipeline, NO cvt in hot loop.
// TF32OUT: round C to tf32-canonical on store (for GEMM-consumed outputs).
#define APAD 20
#define BPAD 136
#define NSTAGE 5
#define AW (128*APAD)

template <bool TRANSB, int ACT, bool RES, bool TF32OUT>
__global__ __launch_bounds__(256, 2) void gemm_tc(
    const float* __restrict__ A, const float* __restrict__ B,
    const float* __restrict__ bias, const float* __restrict__ res,
    float* __restrict__ C, int M, int N, int K) {
    constexpr int BW = TRANSB ? 128 * APAD : 16 * BPAD;
    constexpr int SW = AW + BW;
    extern __shared__ float gsm[];

    const int tid  = threadIdx.x;
    const int lane = tid & 31, warp = tid >> 5;
    const int wm = warp >> 1, wn = warp & 1;
    const int m0 = blockIdx.y * 128, n0 = blockIdx.x * 128;
    const unsigned sbase = (unsigned)__cvta_generic_to_shared(gsm);

    float acc[2][8][4];
    #pragma unroll
    for (int i = 0; i < 2; i++)
        #pragma unroll
        for (int j = 0; j < 8; j++)
            #pragma unroll
            for (int q = 0; q < 4; q++) acc[i][j][q] = 0.0f;

    const int arow = tid >> 1, akoff = (tid & 1) * 8;
    const int brow = tid >> 4, bnoff = (tid & 15) * 8;
    const int tbn  = tid >> 1, tbk   = (tid & 1) * 8;

    auto issue = [&](int stg, int k0) {
        const float* ap = A + (size_t)(m0 + arow) * K + k0 + akoff;
        unsigned ad = sbase + (stg * SW + arow * APAD + akoff) * 4;
        cp16(ad, ap); cp16(ad + 16, ap + 4);
        if (!TRANSB) {
            const float* bp = B + (size_t)(k0 + brow) * N + n0 + bnoff;
            unsigned bd = sbase + (stg * SW + AW + brow * BPAD + bnoff) * 4;
            cp16(bd, bp); cp16(bd + 16, bp + 4);
        } else {
            const float* bp = B + (size_t)(n0 + tbn) * K + k0 + tbk;
            unsigned bd = sbase + (stg * SW + AW + tbn * APAD + tbk) * 4;
            cp16(bd, bp); cp16(bd + 16, bp + 4);
        }
    };

    const int nslab = K / 16;
    #pragma unroll
    for (int s = 0; s < NSTAGE - 1; s++) {
        if (s < nslab) issue(s, s * 16);
        cp_commit();
    }

    for (int i = 0; i < nslab; i++) {
        cp_wait<NSTAGE - 2>();
        __syncthreads();

        const unsigned* Asf = (const unsigned*)(gsm + (i % NSTAGE) * SW);
        const unsigned* Bsf = Asf + AW;

        #pragma unroll
        for (int ks = 0; ks < 2; ks++) {
            const int kb = ks * 8;
            unsigned af[2][4], bf[8][2];
            #pragma unroll
            for (int mt = 0; mt < 2; mt++) {
                int m = wm * 32 + mt * 16 + (lane >> 2);
                int k = kb + (lane & 3);
                af[mt][0] = Asf[m * APAD + k];
                af[mt][1] = Asf[(m + 8) * APAD + k];
                af[mt][2] = Asf[m * APAD + k + 4];
                af[mt][3] = Asf[(m + 8) * APAD + k + 4];
            }
            #pragma unroll
            for (int nt = 0; nt < 8; nt++) {
                int n = wn * 64 + nt * 8 + (lane >> 2);
                int k = kb + (lane & 3);
                if (!TRANSB) {
                    bf[nt][0] = Bsf[k * BPAD + n];
                    bf[nt][1] = Bsf[(k + 4) * BPAD + n];
                } else {
                    bf[nt][0] = Bsf[n * APAD + k];
                    bf[nt][1] = Bsf[n * APAD + k + 4];
                }
            }
            #pragma unroll
            for (int mt = 0; mt < 2; mt++)
                #pragma unroll
                for (int nt = 0; nt < 8; nt++)
                    mma_tf32(acc[mt][nt], af[mt], bf[nt]);
        }

        int j = i + NSTAGE - 1;
        if (j < nslab) issue(j % NSTAGE, j * 16);
        cp_commit();
    }

    #pragma unroll
    for (int mt = 0; mt < 2; mt++) {
        int r0 = m0 + wm * 32 + mt * 16 + (lane >> 2);
        #pragma unroll
        for (int nt = 0; nt < 8; nt++) {
            int c0i = n0 + wn * 64 + nt * 8 + 2 * (lane & 3);
            #pragma unroll
            for (int half = 0; half < 2; half++) {
                int r = r0 + half * 8;
                float v0 = acc[mt][nt][half * 2 + 0];
                float v1 = acc[mt][nt][half * 2 + 1];
                if (bias) { v0 += bias[c0i]; v1 += bias[c0i + 1]; }
                if (ACT == 1) {
                    v0 = v0 * (1.0f / (1.0f + __expf(-v0)));
                    v1 = v1 * (1.0f / (1.0f + __expf(-v1)));
                }
                if (RES) {
                    const float* rp = res + (size_t)r * N + c0i;
                    v0 += rp[0]; v1 += rp[1];
                }
                if (TF32OUT) { v0 = f2tf(v0); v1 = f2tf(v1); }
                float2* cp = (float2*)(C + (size_t)r * N + c0i);
                *cp = make_float2(v0, v1);
            }
        }
    }
}
#define GEMM_SMEM_NT (NSTAGE * (AW + 16 * BPAD) * 4)
#define GEMM_SMEM_T  (NSTAGE * (AW + 128 * APAD) * 4)

// ---------------- flash attention: 64 queries x one (b,h) per block ------------
// qkv is tf32-canonical; output written tf32-rounded.
#define QPAD 68
#define VPAD 72
#define ATTN_SMEM ((64*QPAD + 64*QPAD + 64*VPAD + 64*QPAD + 3*64) * 4)

__global__ __launch_bounds__(256) void attn_flash_k(
    const float* __restrict__ qkv, float* __restrict__ out) {
    extern __shared__ unsigned smem[];
    unsigned* Qs = smem;
    unsigned* Ks = Qs + 64 * QPAD;
    unsigned* Vs = Ks + 64 * QPAD;
    float*    Ss = (float*)(Vs + 64 * VPAD);
    float*    m_sm = Ss + 64 * QPAD;
    float*    l_sm = m_sm + 64;
    float*    sc_sm = l_sm + 64;

    const int q0 = blockIdx.x * 64;
    const int h  = blockIdx.y;
    const int b  = blockIdx.z;
    const int tid = threadIdx.x;
    const int lane = tid & 31, warp = tid >> 5;
    const int wm = warp >> 1, wn = warp & 1;

    const float* qbase = qkv + (size_t)(b * Tv) * QKVN + h * HDv;
    const float* kbase = qbase + Hv * HDv;
    const float* vbase = qbase + 2 * Hv * HDv;

    #pragma unroll
    for (int it = 0; it < 4; it++) {
        int e = tid + 256 * it;
        int r = e >> 4, d = (e & 15) * 4;
        float4 q4 = *(const float4*)(qbase + (size_t)(q0 + r) * QKVN + d);
        unsigned* dst = Qs + r * QPAD + d;
        // inputs tf32-canonical; *0.125f exact -> value == f2t(raw*0.125)
        dst[0] = __float_as_uint(q4.x * 0.125f);
        dst[1] = __float_as_uint(q4.y * 0.125f);
        dst[2] = __float_as_uint(q4.z * 0.125f);
        dst[3] = __float_as_uint(q4.w * 0.125f);
    }
    if (tid < 64) { m_sm[tid] = -1e30f; l_sm[tid] = 0.0f; }

    float acc_o[4][4];
    #pragma unroll
    for (int i = 0; i < 4; i++)
        #pragma unroll
        for (int j = 0; j < 4; j++) acc_o[i][j] = 0.0f;

    for (int c0 = 0; c0 <= q0; c0 += 64) {
        #pragma unroll
        for (int it = 0; it < 4; it++) {
            int e = tid + 256 * it;
            int r = e >> 4, d = (e & 15) * 4;
            float4 k4 = *(const float4*)(kbase + (size_t)(c0 + r) * QKVN + d);
            unsigned* kd = Ks + r * QPAD + d;
            kd[0] = __float_as_uint(k4.x); kd[1] = __float_as_uint(k4.y);
            kd[2] = __float_as_uint(k4.z); kd[3] = __float_as_uint(k4.w);
            float4 v4 = *(const float4*)(vbase + (size_t)(c0 + r) * QKVN + d);
            unsigned* vd = Vs + r * VPAD + d;
            vd[0] = __float_as_uint(v4.x); vd[1] = __float_as_uint(v4.y);
            vd[2] = __float_as_uint(v4.z); vd[3] = __float_as_uint(v4.w);
        }
        __syncthreads();

        float s_acc[4][4];
        #pragma unroll
        for (int i = 0; i < 4; i++)
            #pragma unroll
            for (int j = 0; j < 4; j++) s_acc[i][j] = 0.0f;
        #pragma unroll
        for (int kb = 0; kb < 64; kb += 8) {
            unsigned af[4], bf[4][2];
            int mr = wm * 16 + (lane >> 2);
            int kk = kb + (lane & 3);
            af[0] = Qs[mr * QPAD + kk];
            af[1] = Qs[(mr + 8) * QPAD + kk];
            af[2] = Qs[mr * QPAD + kk + 4];
            af[3] = Qs[(mr + 8) * QPAD + kk + 4];
            #pragma unroll
            for (int nt = 0; nt < 4; nt++) {
                int n = wn * 32 + nt * 8 + (lane >> 2);
                bf[nt][0] = Ks[n * QPAD + kb + (lane & 3)];
                bf[nt][1] = Ks[n * QPAD + kb + (lane & 3) + 4];
            }
            #pragma unroll
            for (int nt = 0; nt < 4; nt++)
                mma_tf32(s_acc[nt], af, bf[nt]);
        }
        const bool diag = (c0 == q0);
        #pragma unroll
        for (int nt = 0; nt < 4; nt++) {
            int c = wn * 32 + nt * 8 + 2 * (lane & 3);
            #pragma unroll
            for (int half = 0; half < 2; half++) {
                int r = wm * 16 + (lane >> 2) + half * 8;
                float v0 = s_acc[nt][half * 2 + 0];
                float v1 = s_acc[nt][half * 2 + 1];
                if (diag) {
                    if (c     > r) v0 = -1e30f;
                    if (c + 1 > r) v1 = -1e30f;
                }
                Ss[r * QPAD + c] = v0; Ss[r * QPAD + c + 1] = v1;
            }
        }
        __syncthreads();

        {
            int r = tid >> 2, g = tid & 3;
            float* row = Ss + r * QPAD;
            float cmax = -1e30f;
            #pragma unroll
            for (int j = 0; j < 16; j++) cmax = fmaxf(cmax, row[g + 4 * j]);
            cmax = fmaxf(cmax, __shfl_xor_sync(0xffffffffu, cmax, 1));
            cmax = fmaxf(cmax, __shfl_xor_sync(0xffffffffu, cmax, 2));
            float m_old = m_sm[r];
            float m_new = fmaxf(m_old, cmax);
            float csum = 0.0f;
            unsigned* prow = (unsigned*)row;
            #pragma unroll
            for (int j = 0; j < 16; j++) {
                float p = __expf(row[g + 4 * j] - m_new);
                csum += p;
                prow[g + 4 * j] = f2t(p);
            }
            csum += __shfl_xor_sync(0xffffffffu, csum, 1);
            csum += __shfl_xor_sync(0xffffffffu, csum, 2);
            if (g == 0) {
                float scale = __expf(m_old - m_new);
                sc_sm[r] = scale;
                l_sm[r] = l_sm[r] * scale + csum;
                m_sm[r] = m_new;
            }
        }
        __syncthreads();

        {
            int r1 = wm * 16 + (lane >> 2);
            float s1 = sc_sm[r1], s2 = sc_sm[r1 + 8];
            #pragma unroll
            for (int nt = 0; nt < 4; nt++) {
                acc_o[nt][0] *= s1; acc_o[nt][1] *= s1;
                acc_o[nt][2] *= s2; acc_o[nt][3] *= s2;
            }
        }
        const unsigned* Pu = (const unsigned*)Ss;
        #pragma unroll
        for (int kb = 0; kb < 64; kb += 8) {
            unsigned af[4], bf[4][2];
            int mr = wm * 16 + (lane >> 2);
            int kk = kb + (lane & 3);
            af[0] = Pu[mr * QPAD + kk];
            af[1] = Pu[(mr + 8) * QPAD + kk];
            af[2] = Pu[mr * QPAD + kk + 4];
            af[3] = Pu[(mr + 8) * QPAD + kk + 4];
            #pragma unroll
            for (int nt = 0; nt < 4; nt++) {
                int n = wn * 32 + nt * 8 + (lane >> 2);
                bf[nt][0] = Vs[(kb + (lane & 3)) * VPAD + n];
                bf[nt][1] = Vs[(kb + (lane & 3) + 4) * VPAD + n];
            }
            #pragma unroll
            for (int nt = 0; nt < 4; nt++)
                mma_tf32(acc_o[nt], af, bf[nt]);
        }
        __syncthreads();
    }

    {
        int r1 = wm * 16 + (lane >> 2);
        float inv1 = 1.0f / l_sm[r1], inv2 = 1.0f / l_sm[r1 + 8];
        #pragma unroll
        for (int nt = 0; nt < 4; nt++) {
            int c = wn * 32 + nt * 8 + 2 * (lane & 3);
            float* o1 = out + (size_t)(b * Tv + q0 + r1) * Dv + h * HDv + c;
            float* o2 = out + (size_t)(b * Tv + q0 + r1 + 8) * Dv + h * HDv + c;
            o1[0] = f2tf(acc_o[nt][0] * inv1); o1[1] = f2tf(acc_o[nt][1] * inv1);
            o2[0] = f2tf(acc_o[nt][2] * inv2); o2[1] = f2tf(acc_o[nt][3] * inv2);
        }
    }
}

// ---------------- driver ----------------
extern "C" void kernel_launch(void* const* d_in, const int* in_sizes, int n_in,
                              void* d_out, int out_size) {
    const int*   ids   = (const int*)  d_in[0];
    const float* te    = (const float*)d_in[1];
    const float* pe    = (const float*)d_in[2];
    const float* ln1_s = (const float*)d_in[3];
    const float* ln1_b = (const float*)d_in[4];
    const float* qkv_w = (const float*)d_in[5];
    const float* qkv_b = (const float*)d_in[6];
    const float* out_w = (const float*)d_in[7];
    const float* out_b = (const float*)d_in[8];
    const float* ln2_s = (const float*)d_in[9];
    const float* ln2_b = (const float*)d_in[10];
    const float* up_w  = (const float*)d_in[11];
    const float* up_b  = (const float*)d_in[12];
    const float* dn_w  = (const float*)d_in[13];
    const float* dn_b  = (const float*)d_in[14];
    const float* lnf_s = (const float*)d_in[15];
    const float* lnf_b = (const float*)d_in[16];
    float* logits = (float*)d_out;

    float *x, *lnb, *qkv, *att, *ff;
    float *wqkv, *wout, *wup, *wdn, *tet;
    cudaGetSymbolAddress((void**)&x,    g_x);
    cudaGetSymbolAddress((void**)&lnb,  g_ln);
    cudaGetSymbolAddress((void**)&qkv,  g_qkv);
    cudaGetSymbolAddress((void**)&att,  g_att);
    cudaGetSymbolAddress((void**)&ff,   g_ff);
    cudaGetSymbolAddress((void**)&wqkv, g_wqkv);
    cudaGetSymbolAddress((void**)&wout, g_wout);
    cudaGetSymbolAddress((void**)&wup,  g_wup);
    cudaGetSymbolAddress((void**)&wdn,  g_wdn);
    cudaGetSymbolAddress((void**)&tet,  g_te);

    cudaFuncSetAttribute(attn_flash_k,
                         cudaFuncAttributeMaxDynamicSharedMemorySize, ATTN_SMEM);
    cudaFuncSetAttribute(gemm_tc<false, 0, false, true>,
                         cudaFuncAttributeMaxDynamicSharedMemorySize, GEMM_SMEM_NT);
    cudaFuncSetAttribute(gemm_tc<false, 0, true, false>,
                         cudaFuncAttributeMaxDynamicSharedMemorySize, GEMM_SMEM_NT);
    cudaFuncSetAttribute(gemm_tc<false, 1, false, true>,
                         cudaFuncAttributeMaxDynamicSharedMemorySize, GEMM_SMEM_NT);
    cudaFuncSetAttribute(gemm_tc<true, 0, false, false>,
                         cudaFuncAttributeMaxDynamicSharedMemorySize, GEMM_SMEM_T);

    // weight pre-conversion to tf32-canonical fp32
    {
        int n;
        n = Lv * Dv * QKVN / 4; cvt_k<<<(n + 255) / 256, 256>>>(qkv_w, wqkv, n);
        n = Lv * Dv * Dv   / 4; cvt_k<<<(n + 255) / 256, 256>>>(out_w, wout, n);
        n = Lv * Dv * DFv  / 4; cvt_k<<<(n + 255) / 256, 256>>>(up_w,  wup,  n);
        n = Lv * DFv * Dv  / 4; cvt_k<<<(n + 255) / 256, 256>>>(dn_w,  wdn,  n);
        n = Vv * Dv        / 4; cvt_k<<<(n + 255) / 256, 256>>>(te,    tet,  n);
    }

    embed_k<<<(Mv * Dv + 255) / 256, 256>>>(ids, te, pe, x);

    for (int i = 0; i < Lv; i++) {
        ln_k<<<Mv, 256>>>(x, ln1_s + (size_t)i * Dv, ln1_b + (size_t)i * Dv, lnb);
        gemm_tc<false, 0, false, true><<<dim3(QKVN / 128, Mv / 128), 256, GEMM_SMEM_NT>>>(
            lnb, wqkv + (size_t)i * Dv * QKVN, qkv_b + (size_t)i * QKVN,
            nullptr, qkv, Mv, QKVN, Dv);
        attn_flash_k<<<dim3(Tv / 64, Hv, Bv), 256, ATTN_SMEM>>>(qkv, att);
        gemm_tc<false, 0, true, false><<<dim3(Dv / 128, Mv / 128), 256, GEMM_SMEM_NT>>>(
            att, wout + (size_t)i * Dv * Dv, out_b + (size_t)i * Dv,
            x, x, Mv, Dv, Dv);
        ln_k<<<Mv, 256>>>(x, ln2_s + (size_t)i * Dv, ln2_b + (size_t)i * Dv, lnb);
        gemm_tc<false, 1, false, true><<<dim3(DFv / 128, Mv / 128), 256, GEMM_SMEM_NT>>>(
            lnb, wup + (size_t)i * Dv * DFv, up_b + (size_t)i * DFv,
            nullptr, ff, Mv, DFv, Dv);
        gemm_tc<false, 0, true, false><<<dim3(Dv / 128, Mv / 128), 256, GEMM_SMEM_NT>>>(
            ff, wdn + (size_t)i * DFv * Dv, dn_b + (size_t)i * Dv,
            x, x, Mv, Dv, DFv);
    }

    ln_k<<<Mv, 256>>>(x, lnf_s, lnf_b, lnb);
    gemm_tc<true, 0, false, false><<<dim3(Vv / 128, Mv / 128), 256, GEMM_SMEM_T>>>(
        lnb, tet, nullptr, nullptr, logits, Mv, Vv, Dv);
}